// round 5
// baseline (speedup 1.0000x reference)
#include <cuda_runtime.h>
#include <cuda_bf16.h>
#include <cstdint>
#include <math.h>

// Problem dimensions (fixed by the reference)
#define BATCH 8
#define SEQ   8192
#define DIM   512
#define HID   512
#define OUTD  512
#define MROWS (BATCH*SEQ)      // 65536
#define CHUNK 128
#define NCH   (SEQ/CHUNK)      // 64

// ---------------------------------------------------------------------------
// Device scratch (no runtime allocation allowed)
// ---------------------------------------------------------------------------
static __device__ float g_lc[(size_t)MROWS*HID];          // log_coeffs
static __device__ float g_lv[(size_t)MROWS*HID];          // log_values
static __device__ __nv_bfloat16 g_hhi[(size_t)MROWS*HID]; // h hi (bf16)
static __device__ __nv_bfloat16 g_hlo[(size_t)MROWS*HID]; // h lo (bf16)
static __device__ float g_A  [(size_t)BATCH*NCH*HID];
static __device__ float g_LVc[(size_t)BATCH*NCH*HID];
static __device__ float g_hin[(size_t)BATCH*NCH*HID];
static __device__ __nv_bfloat16 g_xhi[(size_t)MROWS*DIM];
static __device__ __nv_bfloat16 g_xlo[(size_t)MROWS*DIM];
static __device__ __nv_bfloat16 g_whi[(size_t)2*HID*DIM];
static __device__ __nv_bfloat16 g_wlo[(size_t)2*HID*DIM];
static __device__ __nv_bfloat16 g_ohi[(size_t)OUTD*HID];
static __device__ __nv_bfloat16 g_olo[(size_t)OUTD*HID];

// ---------------------------------------------------------------------------
// PTX helpers (sm_80+ only; no 'a'-suffix features)
// ---------------------------------------------------------------------------
__device__ __forceinline__ uint32_t smem_u32(const void* p) {
    uint32_t a;
    asm("{ .reg .u64 t; cvta.to.shared.u64 t, %1; cvt.u32.u64 %0, t; }" : "=r"(a) : "l"(p));
    return a;
}

#define CP_ASYNC16(dst, src) \
    asm volatile("cp.async.cg.shared.global [%0], [%1], 16;" :: "r"(dst), "l"(src))
#define CP_COMMIT() asm volatile("cp.async.commit_group;" ::: "memory")
#define CP_WAIT(N)  asm volatile("cp.async.wait_group %0;" :: "n"(N) : "memory")

#define LDMX4(r0, r1, r2, r3, a) \
    asm volatile("ldmatrix.sync.aligned.m8n8.x4.shared.b16 {%0,%1,%2,%3}, [%4];" \
        : "=r"(r0), "=r"(r1), "=r"(r2), "=r"(r3) : "r"(a))

#define MMA16816(c0, c1, c2, c3, a0, a1, a2, a3, b0, b1) \
    asm volatile("mma.sync.aligned.m16n8k16.row.col.f32.bf16.bf16.f32 " \
        "{%0,%1,%2,%3}, {%4,%5,%6,%7}, {%8,%9}, {%0,%1,%2,%3};" \
        : "+f"(c0), "+f"(c1), "+f"(c2), "+f"(c3) \
        : "r"(a0), "r"(a1), "r"(a2), "r"(a3), "r"(b0), "r"(b1))

// ---------------------------------------------------------------------------
// Math helpers
// ---------------------------------------------------------------------------
__device__ __forceinline__ float sp_f(float x) {
    return fmaxf(x, 0.0f) + log1pf(__expf(-fabsf(x)));
}
__device__ __forceinline__ float lae(float a, float b) {
    float m = fmaxf(a, b);
    return m + log1pf(__expf(-fabsf(a - b)));
}

// ---------------------------------------------------------------------------
// fp32 -> bf16 hi/lo split conversion
// ---------------------------------------------------------------------------
__global__ __launch_bounds__(256) void cvt_kernel(const float* __restrict__ src,
                                                  __nv_bfloat16* __restrict__ hi,
                                                  __nv_bfloat16* __restrict__ lo) {
    const size_t i = (size_t)blockIdx.x * blockDim.x + threadIdx.x;
    float4 v = ((const float4*)src)[i];
    __nv_bfloat16 hx = __float2bfloat16(v.x), hy = __float2bfloat16(v.y);
    __nv_bfloat16 hz = __float2bfloat16(v.z), hw = __float2bfloat16(v.w);
    __nv_bfloat16 lx = __float2bfloat16(v.x - __bfloat162float(hx));
    __nv_bfloat16 ly = __float2bfloat16(v.y - __bfloat162float(hy));
    __nv_bfloat16 lz = __float2bfloat16(v.z - __bfloat162float(hz));
    __nv_bfloat16 lw = __float2bfloat16(v.w - __bfloat162float(hw));
    ((__nv_bfloat162*)hi)[2*i]   = __nv_bfloat162(hx, hy);
    ((__nv_bfloat162*)hi)[2*i+1] = __nv_bfloat162(hz, hw);
    ((__nv_bfloat162*)lo)[2*i]   = __nv_bfloat162(lx, ly);
    ((__nv_bfloat162*)lo)[2*i+1] = __nv_bfloat162(lz, lw);
}

// ---------------------------------------------------------------------------
// mma.sync GEMM mainloop. Block 128Mx128N, 512 threads (16 warps, warp tile
// 32x32), K=512, kc=32, THREE cp.async stages. Split precision:
// acc += Ahi*Bhi + Ahi*Blo + Alo*Bhi (fp32 acc).
//
// SMEM stage layout (bytes from stage base), row stride 80B (40 bf16):
//   Ahi [0,10240)  Alo [10240,20480)  Bhi [20480,30720)  Blo [30720,40960)
// Stage = 40960B, 3 stages = 122880B (epilogue staging reuses this space).
//
// INTERLEAVE (GEMM1): B-tile n-row r maps to W_hg row (r even: nb + r/2
// hidden; r odd: 512 + nb + r/2 gate) so accumulator col pairs are
// (hidden, gate) of the same channel.
// ---------------------------------------------------------------------------
#define STG_B   40960
#define NSTAGE  3
#define SMEM_BYTES (NSTAGE*STG_B)

template<bool INTERLEAVE>
__device__ __forceinline__ void gemm_mainloop(const __nv_bfloat16* __restrict__ Ahi,
                                              const __nv_bfloat16* __restrict__ Alo,
                                              const __nv_bfloat16* __restrict__ Bhi,
                                              const __nv_bfloat16* __restrict__ Blo,
                                              int m0, int nb, uint32_t sbase,
                                              float acc[2][4][4]) {
    const int tid  = threadIdx.x;
    const int lane = tid & 31;
    const int wid  = tid >> 5;
    const int wm   = (wid >> 2) * 32;   // warp M offset (0/32/64/96)
    const int wn   = (wid & 3) * 32;    // warp N offset (0/32/64/96)

#pragma unroll
    for (int mi = 0; mi < 2; mi++)
#pragma unroll
        for (int ni = 0; ni < 4; ni++)
#pragma unroll
            for (int e = 0; e < 4; e++) acc[mi][ni][e] = 0.0f;

    // ---- stage loader: 4 cp.asyncs per thread (A hi/lo + B hi/lo) ----
    auto load_stage = [&](int j, int s) {
        const uint32_t st = sbase + s * STG_B;
        const int k0 = j * 32;
        const int r = tid >> 2, c = tid & 3;          // 512 chunks of 16B
        const uint32_t so = (uint32_t)(r * 80 + c * 16);
        {   // A
            const size_t go = (size_t)(m0 + r) * 512 + k0 + c * 8;
            CP_ASYNC16(st + so,         (const void*)(Ahi + go));
            CP_ASYNC16(st + 10240 + so, (const void*)(Alo + go));
        }
        {   // B
            int wr;
            if (INTERLEAVE) wr = (r & 1) ? (512 + nb + (r >> 1)) : (nb + (r >> 1));
            else            wr = nb + r;
            const size_t go = (size_t)wr * 512 + k0 + c * 8;
            CP_ASYNC16(st + 20480 + so, (const void*)(Bhi + go));
            CP_ASYNC16(st + 30720 + so, (const void*)(Blo + go));
        }
        CP_COMMIT();
    };

    load_stage(0, 0);
    load_stage(1, 1);

    for (int j = 0; j < 16; j++) {
        __syncthreads();   // all reads of the stage being overwritten are done
        if (j <= 13) { load_stage(j + 2, (j + 2) % 3); CP_WAIT(2); }
        else if (j == 14) { CP_WAIT(1); }
        else              { CP_WAIT(0); }
        __syncthreads();   // stage j visible to all warps

        const uint32_t st = sbase + (j % 3) * STG_B;
#pragma unroll
        for (int s = 0; s < 2; s++) {          // two k16 steps per stage
            // ---- B fragments: 4 n8 tiles, hi+lo ----
            uint32_t bh[4][2], bl[4][2];
#pragma unroll
            for (int p = 0; p < 2; p++) {
                const int nr = wn + p * 16 + (lane & 7) + ((lane & 16) ? 8 : 0);
                const int ko = s * 16 + ((lane & 8) ? 8 : 0);
                const uint32_t ba = st + 20480 + (uint32_t)(nr * 80 + ko * 2);
                LDMX4(bh[p*2][0], bh[p*2][1], bh[p*2+1][0], bh[p*2+1][1], ba);
                LDMX4(bl[p*2][0], bl[p*2][1], bl[p*2+1][0], bl[p*2+1][1], ba + 10240);
            }
            // ---- A fragments per m16 tile + MMAs ----
#pragma unroll
            for (int mi = 0; mi < 2; mi++) {
                const int mr = wm + mi * 16 + (lane & 15);
                const int ko = s * 16 + ((lane & 16) ? 8 : 0);
                const uint32_t aa = st + (uint32_t)(mr * 80 + ko * 2);
                uint32_t ah[4], al[4];
                LDMX4(ah[0], ah[1], ah[2], ah[3], aa);
                LDMX4(al[0], al[1], al[2], al[3], aa + 10240);
#pragma unroll
                for (int ni = 0; ni < 4; ni++) {
                    MMA16816(acc[mi][ni][0], acc[mi][ni][1], acc[mi][ni][2], acc[mi][ni][3],
                             ah[0], ah[1], ah[2], ah[3], bh[ni][0], bh[ni][1]);
                    MMA16816(acc[mi][ni][0], acc[mi][ni][1], acc[mi][ni][2], acc[mi][ni][3],
                             ah[0], ah[1], ah[2], ah[3], bl[ni][0], bl[ni][1]);
                    MMA16816(acc[mi][ni][0], acc[mi][ni][1], acc[mi][ni][2], acc[mi][ni][3],
                             al[0], al[1], al[2], al[3], bh[ni][0], bh[ni][1]);
                }
            }
        }
    }
}

// ---------------------------------------------------------------------------
// GEMM1: hg = x @ W_hg^T with fused lc/lv epilogue (interleaved channels).
// Grid: (HID/64, MROWS/128). Each block: 128 rows x 64 channels.
// ---------------------------------------------------------------------------
__global__ __launch_bounds__(512, 1)
void gemm1_mma() {
    extern __shared__ __align__(128) char smem[];
    const uint32_t sbase = smem_u32(smem);
    const int m0 = blockIdx.y * 128;
    const int nb = blockIdx.x * 64;

    float acc[2][4][4];
    gemm_mainloop<true>(g_xhi, g_xlo, g_whi, g_wlo, m0, nb, sbase, acc);

    // Epilogue: compute lc/lv in regs, stage via smem (stride 76 floats),
    // then coalesced float4 writes.
    __syncthreads();
    float* lcs = (float*)smem;            // [128][76]
    float* lvs = lcs + 128 * 76;          // [128][76]
    const int tid = threadIdx.x, lane = tid & 31, wid = tid >> 5;
    const int wm = (wid >> 2) * 32;
    const int wn = (wid & 3) * 32;

#pragma unroll
    for (int mi = 0; mi < 2; mi++) {
#pragma unroll
        for (int ni = 0; ni < 4; ni++) {
            const int j  = (wn >> 1) + ni * 4 + (lane & 3);   // channel 0..63
            const int r0 = wm + mi * 16 + (lane >> 2);
#pragma unroll
            for (int e = 0; e < 2; e++) {
                const int r = r0 + e * 8;
                const float hv = acc[mi][ni][2*e];
                const float gv = acc[mi][ni][2*e + 1];
                const float lgv = (hv >= 0.0f) ? __logf(hv + 0.5f) : -sp_f(-hv);
                lcs[r * 76 + j] = -sp_f(gv);
                lvs[r * 76 + j] = lgv - sp_f(-gv);
            }
        }
    }
    __syncthreads();

    for (int idx = tid; idx < 2048; idx += 512) {
        const int r = idx >> 4, q = idx & 15;
        const size_t go = (size_t)(m0 + r) * HID + nb + q * 4;
        *(float4*)(g_lc + go) = *(float4*)&lcs[r * 76 + q * 4];
        *(float4*)(g_lv + go) = *(float4*)&lvs[r * 76 + q * 4];
    }
}

// ---------------------------------------------------------------------------
// GEMM2: out = h @ W_out^T. Grid: (OUTD/128, MROWS/128). Direct f32x2 stores.
// ---------------------------------------------------------------------------
__global__ __launch_bounds__(512, 1)
void gemm2_mma(float* __restrict__ out) {
    extern __shared__ __align__(128) char smem[];
    const uint32_t sbase = smem_u32(smem);
    const int m0 = blockIdx.y * 128;
    const int nb = blockIdx.x * 128;

    float acc[2][4][4];
    gemm_mainloop<false>(g_hhi, g_hlo, g_ohi, g_olo, m0, nb, sbase, acc);

    const int tid = threadIdx.x, lane = tid & 31, wid = tid >> 5;
    const int wm = (wid >> 2) * 32;
    const int wn = (wid & 3) * 32;

#pragma unroll
    for (int mi = 0; mi < 2; mi++) {
#pragma unroll
        for (int ni = 0; ni < 4; ni++) {
            const int col = nb + wn + ni * 8 + (lane & 3) * 2;
            const int r0  = m0 + wm + mi * 16 + (lane >> 2);
            *(float2*)(out + (size_t)r0 * OUTD + col)
                = make_float2(acc[mi][ni][0], acc[mi][ni][1]);
            *(float2*)(out + (size_t)(r0 + 8) * OUTD + col)
                = make_float2(acc[mi][ni][2], acc[mi][ni][3]);
        }
    }
}

// ---------------------------------------------------------------------------
// Chunked log-space scan (pass3 emits bf16 hi/lo h)
// ---------------------------------------------------------------------------
__global__ __launch_bounds__(512) void scan_pass1() {
    const int b = blockIdx.y, c = blockIdx.x, h = threadIdx.x;
    size_t base = ((size_t)(b * SEQ + c * CHUNK)) * HID + h;
    float A = 0.0f, LV = -1e30f;
    for (int t = 0; t < CHUNK; t++) {
        const float lc = g_lc[base];
        const float lv = g_lv[base];
        LV = lae(lc + LV, lv);
        A += lc;
        base += HID;
    }
    const size_t si = ((size_t)(b * NCH + c)) * HID + h;
    g_A[si]   = A;
    g_LVc[si] = LV;
}

__global__ __launch_bounds__(512) void scan_pass2() {
    const int b = blockIdx.x, h = threadIdx.x;
    float run = -1e30f;
    for (int c = 0; c < NCH; c++) {
        const size_t si = ((size_t)(b * NCH + c)) * HID + h;
        g_hin[si] = run;
        run = lae(g_A[si] + run, g_LVc[si]);
    }
}

__global__ __launch_bounds__(512) void scan_pass3(float* __restrict__ out_hn) {
    const int b = blockIdx.y, c = blockIdx.x, h = threadIdx.x;
    const size_t si = ((size_t)(b * NCH + c)) * HID + h;
    float lh = g_hin[si];
    size_t base = ((size_t)(b * SEQ + c * CHUNK)) * HID + h;
    float hv = 0.0f;
    for (int t = 0; t < CHUNK; t++) {
        lh = lae(g_lc[base] + lh, g_lv[base]);
        hv = __expf(lh);
        const __nv_bfloat16 hh = __float2bfloat16(hv);
        g_hhi[base] = hh;
        g_hlo[base] = __float2bfloat16(hv - __bfloat162float(hh));
        base += HID;
    }
    if (c == NCH - 1)
        out_hn[b * HID + h] = hv;
}

// ---------------------------------------------------------------------------
// Launch. Inputs: x f32 (8,8192,512) | is_init bool(8) | W_hg f32 (1024,512)
// | W_out f32 (512,512). Output: out f32 (B,S,O) ++ h_n f32 (B,1,H).
// ---------------------------------------------------------------------------
extern "C" void kernel_launch(void* const* d_in, const int* in_sizes, int n_in,
                              void* d_out, int out_size) {
    (void)in_sizes; (void)n_in; (void)out_size;
    const float* x    = (const float*)d_in[0];
    const float* Whg  = (const float*)d_in[2];
    const float* Wout = (const float*)d_in[3];
    float* out    = (float*)d_out;
    float* out_hn = out + (size_t)MROWS * OUTD;

    cudaFuncSetAttribute((const void*)gemm1_mma,
                         cudaFuncAttributeMaxDynamicSharedMemorySize, SMEM_BYTES);
    cudaFuncSetAttribute((const void*)gemm2_mma,
                         cudaFuncAttributeMaxDynamicSharedMemorySize, SMEM_BYTES);

    __nv_bfloat16 *xhi, *xlo, *whi, *wlo, *ohi, *olo;
    cudaGetSymbolAddress((void**)&xhi, g_xhi);
    cudaGetSymbolAddress((void**)&xlo, g_xlo);
    cudaGetSymbolAddress((void**)&whi, g_whi);
    cudaGetSymbolAddress((void**)&wlo, g_wlo);
    cudaGetSymbolAddress((void**)&ohi, g_ohi);
    cudaGetSymbolAddress((void**)&olo, g_olo);

    // bf16 hi/lo conversion prepass
    cvt_kernel<<<(MROWS * (size_t)DIM) / 4 / 256, 256>>>(x, xhi, xlo);
    cvt_kernel<<<(2 * HID * (size_t)DIM) / 4 / 256, 256>>>(Whg, whi, wlo);
    cvt_kernel<<<(OUTD * (size_t)HID) / 4 / 256, 256>>>(Wout, ohi, olo);

    // GEMM1 (mma.sync bf16 split) with fused lc/lv epilogue
    gemm1_mma<<<dim3(HID / 64, MROWS / 128), 512, SMEM_BYTES>>>();

    // scan
    scan_pass1<<<dim3(NCH, BATCH), HID>>>();
    scan_pass2<<<BATCH, HID>>>();
    scan_pass3<<<dim3(NCH, BATCH), HID>>>(out_hn);

    // GEMM2 (mma.sync bf16 split)
    gemm2_mma<<<dim3(OUTD / 128, MROWS / 128), 512, SMEM_BYTES>>>(out);
}

// round 6
// speedup vs baseline: 1.7849x; 1.7849x over previous
#include <cuda_runtime.h>
#include <cuda_bf16.h>
#include <cstdint>
#include <math.h>

// Problem dimensions (fixed by the reference)
#define BATCH 8
#define SEQ   8192
#define DIM   512
#define HID   512
#define OUTD  512
#define MROWS (BATCH*SEQ)      // 65536
#define CHUNK 128
#define NCH   (SEQ/CHUNK)      // 64

// ---------------------------------------------------------------------------
// Device scratch (no runtime allocation allowed)
// ---------------------------------------------------------------------------
static __device__ float g_lc[(size_t)MROWS*HID];          // log_coeffs
static __device__ float g_lv[(size_t)MROWS*HID];          // log_values
static __device__ __nv_bfloat16 g_hhi[(size_t)MROWS*HID]; // h hi (bf16)
static __device__ __nv_bfloat16 g_hlo[(size_t)MROWS*HID]; // h lo (bf16)
static __device__ float g_A  [(size_t)BATCH*NCH*HID];
static __device__ float g_LVc[(size_t)BATCH*NCH*HID];
static __device__ float g_hin[(size_t)BATCH*NCH*HID];
static __device__ __nv_bfloat16 g_xhi[(size_t)MROWS*DIM];
static __device__ __nv_bfloat16 g_xlo[(size_t)MROWS*DIM];
static __device__ __nv_bfloat16 g_whi[(size_t)2*HID*DIM];
static __device__ __nv_bfloat16 g_wlo[(size_t)2*HID*DIM];
static __device__ __nv_bfloat16 g_ohi[(size_t)OUTD*HID];
static __device__ __nv_bfloat16 g_olo[(size_t)OUTD*HID];

// ---------------------------------------------------------------------------
// PTX helpers (sm_80+ only; no 'a'-suffix features)
// ---------------------------------------------------------------------------
__device__ __forceinline__ uint32_t smem_u32(const void* p) {
    uint32_t a;
    asm("{ .reg .u64 t; cvta.to.shared.u64 t, %1; cvt.u32.u64 %0, t; }" : "=r"(a) : "l"(p));
    return a;
}

#define CP_ASYNC16(dst, src) \
    asm volatile("cp.async.cg.shared.global [%0], [%1], 16;" :: "r"(dst), "l"(src))
#define CP_COMMIT() asm volatile("cp.async.commit_group;" ::: "memory")
#define CP_WAIT(N)  asm volatile("cp.async.wait_group %0;" :: "n"(N) : "memory")

#define LDMX4(r0, r1, r2, r3, a) \
    asm volatile("ldmatrix.sync.aligned.m8n8.x4.shared.b16 {%0,%1,%2,%3}, [%4];" \
        : "=r"(r0), "=r"(r1), "=r"(r2), "=r"(r3) : "r"(a))

#define MMA16816(c0, c1, c2, c3, a0, a1, a2, a3, b0, b1) \
    asm volatile("mma.sync.aligned.m16n8k16.row.col.f32.bf16.bf16.f32 " \
        "{%0,%1,%2,%3}, {%4,%5,%6,%7}, {%8,%9}, {%0,%1,%2,%3};" \
        : "+f"(c0), "+f"(c1), "+f"(c2), "+f"(c3) \
        : "r"(a0), "r"(a1), "r"(a2), "r"(a3), "r"(b0), "r"(b1))

// ---------------------------------------------------------------------------
// Math helpers
// ---------------------------------------------------------------------------
__device__ __forceinline__ float sp_f(float x) {
    return fmaxf(x, 0.0f) + log1pf(__expf(-fabsf(x)));
}
__device__ __forceinline__ float lae(float a, float b) {
    float m = fmaxf(a, b);
    return m + log1pf(__expf(-fabsf(a - b)));
}

// ---------------------------------------------------------------------------
// fp32 -> bf16 hi/lo split conversion
// ---------------------------------------------------------------------------
__global__ __launch_bounds__(256) void cvt_kernel(const float* __restrict__ src,
                                                  __nv_bfloat16* __restrict__ hi,
                                                  __nv_bfloat16* __restrict__ lo) {
    const size_t i = (size_t)blockIdx.x * blockDim.x + threadIdx.x;
    float4 v = ((const float4*)src)[i];
    __nv_bfloat16 hx = __float2bfloat16(v.x), hy = __float2bfloat16(v.y);
    __nv_bfloat16 hz = __float2bfloat16(v.z), hw = __float2bfloat16(v.w);
    __nv_bfloat16 lx = __float2bfloat16(v.x - __bfloat162float(hx));
    __nv_bfloat16 ly = __float2bfloat16(v.y - __bfloat162float(hy));
    __nv_bfloat16 lz = __float2bfloat16(v.z - __bfloat162float(hz));
    __nv_bfloat16 lw = __float2bfloat16(v.w - __bfloat162float(hw));
    ((__nv_bfloat162*)hi)[2*i]   = __nv_bfloat162(hx, hy);
    ((__nv_bfloat162*)hi)[2*i+1] = __nv_bfloat162(hz, hw);
    ((__nv_bfloat162*)lo)[2*i]   = __nv_bfloat162(lx, ly);
    ((__nv_bfloat162*)lo)[2*i+1] = __nv_bfloat162(lz, lw);
}

// ---------------------------------------------------------------------------
// mma.sync GEMM mainloop. Block 128Mx128N, 256 threads (8 warps, warp tile
// 64x32), K=512, kc=32, double-buffered cp.async, 2 CTAs/SM. Split precision:
// acc += Ahi*Bhi + Ahi*Blo + Alo*Bhi (fp32 acc).
//
// SMEM stage layout (bytes from stage base), row stride 80B (40 bf16):
//   Ahi [0,10240)  Alo [10240,20480)  Bhi [20480,30720)  Blo [30720,40960)
// Stage = 40960B, 2 stages = 81920B (epilogue staging reuses this space).
//
// INTERLEAVE (GEMM1): B-tile n-row r maps to W_hg row (r even: nb + r/2
// hidden; r odd: 512 + nb + r/2 gate) so accumulator col pairs are
// (hidden, gate) of the same channel.
// ---------------------------------------------------------------------------
#define STG_B   40960
#define SMEM_BYTES (2*STG_B)

template<bool INTERLEAVE>
__device__ __forceinline__ void gemm_mainloop(const __nv_bfloat16* __restrict__ Ahi,
                                              const __nv_bfloat16* __restrict__ Alo,
                                              const __nv_bfloat16* __restrict__ Bhi,
                                              const __nv_bfloat16* __restrict__ Blo,
                                              int m0, int nb, uint32_t sbase,
                                              float acc[4][4][4]) {
    const int tid  = threadIdx.x;
    const int lane = tid & 31;
    const int wid  = tid >> 5;
    const int wm   = (wid >> 2) * 64;   // warp M offset (0/64)
    const int wn   = (wid & 3) * 32;    // warp N offset (0/32/64/96)

#pragma unroll
    for (int mi = 0; mi < 4; mi++)
#pragma unroll
        for (int ni = 0; ni < 4; ni++)
#pragma unroll
            for (int e = 0; e < 4; e++) acc[mi][ni][e] = 0.0f;

    // ---- stage loader: 8 cp.asyncs x 2 iters x 2 arrays per thread ----
    auto load_stage = [&](int j, int s) {
        const uint32_t st = sbase + s * STG_B;
        const int k0 = j * 32;
#pragma unroll
        for (int i = 0; i < 2; i++) {          // A chunks (512 per split)
            const int idx = tid + i * 256;
            const int r = idx >> 2, c = idx & 3;
            const size_t go = (size_t)(m0 + r) * 512 + k0 + c * 8;
            const uint32_t so = (uint32_t)(r * 80 + c * 16);
            CP_ASYNC16(st + so,         (const void*)(Ahi + go));
            CP_ASYNC16(st + 10240 + so, (const void*)(Alo + go));
        }
#pragma unroll
        for (int i = 0; i < 2; i++) {          // B chunks
            const int idx = tid + i * 256;
            const int r = idx >> 2, c = idx & 3;
            int wr;
            if (INTERLEAVE) wr = (r & 1) ? (512 + nb + (r >> 1)) : (nb + (r >> 1));
            else            wr = nb + r;
            const size_t go = (size_t)wr * 512 + k0 + c * 8;
            const uint32_t so = (uint32_t)(r * 80 + c * 16);
            CP_ASYNC16(st + 20480 + so, (const void*)(Bhi + go));
            CP_ASYNC16(st + 30720 + so, (const void*)(Blo + go));
        }
        CP_COMMIT();
    };

    load_stage(0, 0);

    for (int j = 0; j < 16; j++) {
        if (j + 1 < 16) load_stage(j + 1, (j + 1) & 1);
        if (j + 1 < 16) { CP_WAIT(1); } else { CP_WAIT(0); }
        __syncthreads();

        const uint32_t st = sbase + (j & 1) * STG_B;
#pragma unroll
        for (int s = 0; s < 2; s++) {          // two k16 steps per stage
            // ---- B fragments: 4 n-tiles, hi+lo ----
            uint32_t bh[4][2], bl[4][2];
#pragma unroll
            for (int p = 0; p < 2; p++) {
                const int nr = wn + p * 16 + (lane & 7) + ((lane & 16) ? 8 : 0);
                const int ko = s * 16 + ((lane & 8) ? 8 : 0);
                const uint32_t ba = st + 20480 + (uint32_t)(nr * 80 + ko * 2);
                LDMX4(bh[p*2][0], bh[p*2][1], bh[p*2+1][0], bh[p*2+1][1], ba);
                LDMX4(bl[p*2][0], bl[p*2][1], bl[p*2+1][0], bl[p*2+1][1], ba + 10240);
            }
            // ---- A fragments per m-tile + MMAs ----
#pragma unroll
            for (int mi = 0; mi < 4; mi++) {
                const int mr = wm + mi * 16 + (lane & 15);
                const int ko = s * 16 + ((lane & 16) ? 8 : 0);
                const uint32_t aa = st + (uint32_t)(mr * 80 + ko * 2);
                uint32_t ah[4], al[4];
                LDMX4(ah[0], ah[1], ah[2], ah[3], aa);
                LDMX4(al[0], al[1], al[2], al[3], aa + 10240);
#pragma unroll
                for (int ni = 0; ni < 4; ni++) {
                    MMA16816(acc[mi][ni][0], acc[mi][ni][1], acc[mi][ni][2], acc[mi][ni][3],
                             ah[0], ah[1], ah[2], ah[3], bh[ni][0], bh[ni][1]);
                    MMA16816(acc[mi][ni][0], acc[mi][ni][1], acc[mi][ni][2], acc[mi][ni][3],
                             ah[0], ah[1], ah[2], ah[3], bl[ni][0], bl[ni][1]);
                    MMA16816(acc[mi][ni][0], acc[mi][ni][1], acc[mi][ni][2], acc[mi][ni][3],
                             al[0], al[1], al[2], al[3], bh[ni][0], bh[ni][1]);
                }
            }
        }
        __syncthreads();
    }
}

// ---------------------------------------------------------------------------
// GEMM1: hg = x @ W_hg^T with fused lc/lv epilogue (interleaved channels).
// Grid: (HID/64, MROWS/128). Each block: 128 rows x 64 channels.
// ---------------------------------------------------------------------------
__global__ __launch_bounds__(256, 2)
void gemm1_mma() {
    extern __shared__ __align__(128) char smem[];
    const uint32_t sbase = smem_u32(smem);
    const int m0 = blockIdx.y * 128;
    const int nb = blockIdx.x * 64;

    float acc[4][4][4];
    gemm_mainloop<true>(g_xhi, g_xlo, g_whi, g_wlo, m0, nb, sbase, acc);

    // Epilogue: compute lc/lv in regs, stage via smem (stride 76 floats),
    // then coalesced float4 writes.
    float* lcs = (float*)smem;            // [128][76]
    float* lvs = lcs + 128 * 76;          // [128][76]
    const int tid = threadIdx.x, lane = tid & 31, wid = tid >> 5;
    const int wm = (wid >> 2) * 64;
    const int wn = (wid & 3) * 32;

#pragma unroll
    for (int mi = 0; mi < 4; mi++) {
#pragma unroll
        for (int ni = 0; ni < 4; ni++) {
            const int j  = (wn >> 1) + ni * 4 + (lane & 3);   // channel 0..63
            const int r0 = wm + mi * 16 + (lane >> 2);
#pragma unroll
            for (int e = 0; e < 2; e++) {
                const int r = r0 + e * 8;
                const float hv = acc[mi][ni][2*e];
                const float gv = acc[mi][ni][2*e + 1];
                const float lgv = (hv >= 0.0f) ? __logf(hv + 0.5f) : -sp_f(-hv);
                lcs[r * 76 + j] = -sp_f(gv);
                lvs[r * 76 + j] = lgv - sp_f(-gv);
            }
        }
    }
    __syncthreads();

    for (int idx = tid; idx < 2048; idx += 256) {
        const int r = idx >> 4, q = idx & 15;
        const size_t go = (size_t)(m0 + r) * HID + nb + q * 4;
        *(float4*)(g_lc + go) = *(float4*)&lcs[r * 76 + q * 4];
        *(float4*)(g_lv + go) = *(float4*)&lvs[r * 76 + q * 4];
    }
}

// ---------------------------------------------------------------------------
// GEMM2: out = h @ W_out^T. Grid: (OUTD/128, MROWS/128). Direct f32x2 stores.
// ---------------------------------------------------------------------------
__global__ __launch_bounds__(256, 2)
void gemm2_mma(float* __restrict__ out) {
    extern __shared__ __align__(128) char smem[];
    const uint32_t sbase = smem_u32(smem);
    const int m0 = blockIdx.y * 128;
    const int nb = blockIdx.x * 128;

    float acc[4][4][4];
    gemm_mainloop<false>(g_hhi, g_hlo, g_ohi, g_olo, m0, nb, sbase, acc);

    const int tid = threadIdx.x, lane = tid & 31, wid = tid >> 5;
    const int wm = (wid >> 2) * 64;
    const int wn = (wid & 3) * 32;

#pragma unroll
    for (int mi = 0; mi < 4; mi++) {
#pragma unroll
        for (int ni = 0; ni < 4; ni++) {
            const int col = nb + wn + ni * 8 + (lane & 3) * 2;
            const int r0  = m0 + wm + mi * 16 + (lane >> 2);
            *(float2*)(out + (size_t)r0 * OUTD + col)
                = make_float2(acc[mi][ni][0], acc[mi][ni][1]);
            *(float2*)(out + (size_t)(r0 + 8) * OUTD + col)
                = make_float2(acc[mi][ni][2], acc[mi][ni][3]);
        }
    }
}

// ---------------------------------------------------------------------------
// Chunked log-space scan (pass3 emits bf16 hi/lo h)
// ---------------------------------------------------------------------------
__global__ __launch_bounds__(512) void scan_pass1() {
    const int b = blockIdx.y, c = blockIdx.x, h = threadIdx.x;
    size_t base = ((size_t)(b * SEQ + c * CHUNK)) * HID + h;
    float A = 0.0f, LV = -1e30f;
    for (int t = 0; t < CHUNK; t++) {
        const float lc = g_lc[base];
        const float lv = g_lv[base];
        LV = lae(lc + LV, lv);
        A += lc;
        base += HID;
    }
    const size_t si = ((size_t)(b * NCH + c)) * HID + h;
    g_A[si]   = A;
    g_LVc[si] = LV;
}

__global__ __launch_bounds__(512) void scan_pass2() {
    const int b = blockIdx.x, h = threadIdx.x;
    float run = -1e30f;
    for (int c = 0; c < NCH; c++) {
        const size_t si = ((size_t)(b * NCH + c)) * HID + h;
        g_hin[si] = run;
        run = lae(g_A[si] + run, g_LVc[si]);
    }
}

__global__ __launch_bounds__(512) void scan_pass3(float* __restrict__ out_hn) {
    const int b = blockIdx.y, c = blockIdx.x, h = threadIdx.x;
    const size_t si = ((size_t)(b * NCH + c)) * HID + h;
    float lh = g_hin[si];
    size_t base = ((size_t)(b * SEQ + c * CHUNK)) * HID + h;
    float hv = 0.0f;
    for (int t = 0; t < CHUNK; t++) {
        lh = lae(g_lc[base] + lh, g_lv[base]);
        hv = __expf(lh);
        const __nv_bfloat16 hh = __float2bfloat16(hv);
        g_hhi[base] = hh;
        g_hlo[base] = __float2bfloat16(hv - __bfloat162float(hh));
        base += HID;
    }
    if (c == NCH - 1)
        out_hn[b * HID + h] = hv;
}

// ---------------------------------------------------------------------------
// Launch. Inputs: x f32 (8,8192,512) | is_init bool(8) | W_hg f32 (1024,512)
// | W_out f32 (512,512). Output: out f32 (B,S,O) ++ h_n f32 (B,1,H).
// ---------------------------------------------------------------------------
extern "C" void kernel_launch(void* const* d_in, const int* in_sizes, int n_in,
                              void* d_out, int out_size) {
    (void)in_sizes; (void)n_in; (void)out_size;
    const float* x    = (const float*)d_in[0];
    const float* Whg  = (const float*)d_in[2];
    const float* Wout = (const float*)d_in[3];
    float* out    = (float*)d_out;
    float* out_hn = out + (size_t)MROWS * OUTD;

    cudaFuncSetAttribute((const void*)gemm1_mma,
                         cudaFuncAttributeMaxDynamicSharedMemorySize, SMEM_BYTES);
    cudaFuncSetAttribute((const void*)gemm2_mma,
                         cudaFuncAttributeMaxDynamicSharedMemorySize, SMEM_BYTES);

    __nv_bfloat16 *xhi, *xlo, *whi, *wlo, *ohi, *olo;
    cudaGetSymbolAddress((void**)&xhi, g_xhi);
    cudaGetSymbolAddress((void**)&xlo, g_xlo);
    cudaGetSymbolAddress((void**)&whi, g_whi);
    cudaGetSymbolAddress((void**)&wlo, g_wlo);
    cudaGetSymbolAddress((void**)&ohi, g_ohi);
    cudaGetSymbolAddress((void**)&olo, g_olo);

    // bf16 hi/lo conversion prepass
    cvt_kernel<<<(MROWS * (size_t)DIM) / 4 / 256, 256>>>(x, xhi, xlo);
    cvt_kernel<<<(2 * HID * (size_t)DIM) / 4 / 256, 256>>>(Whg, whi, wlo);
    cvt_kernel<<<(OUTD * (size_t)HID) / 4 / 256, 256>>>(Wout, ohi, olo);

    // GEMM1 (mma.sync bf16 split) with fused lc/lv epilogue
    gemm1_mma<<<dim3(HID / 64, MROWS / 128), 256, SMEM_BYTES>>>();

    // scan
    scan_pass1<<<dim3(NCH, BATCH), HID>>>();
    scan_pass2<<<BATCH, HID>>>();
    scan_pass3<<<dim3(NCH, BATCH), HID>>>(out_hn);

    // GEMM2 (mma.sync bf16 split)
    gemm2_mma<<<dim3(OUTD / 128, MROWS / 128), 256, SMEM_BYTES>>>(out);
}